// round 12
// baseline (speedup 1.0000x reference)
#include <cuda_runtime.h>

#define BZ   32
#define CAP  134
#define SEQ  144
#define INV  16
#define E_SP 1072
#define E_FT 64
#define NTHR 160
#define XSTR 152   // 2 zero guard cols + 144 + pad (sX row stride)
#define SOFF 2     // guard offset
#define YSTR 20    // padded row stride for sYA/sYF (80B rows, 16B-aligned)

typedef unsigned long long u64;

// ---------------- f32x2 packed helpers (sm_103a) -----------------------------
__device__ __forceinline__ u64 pack2(float x, float y) {
    u64 r; asm("mov.b64 %0, {%1, %2};" : "=l"(r) : "f"(x), "f"(y)); return r;
}
__device__ __forceinline__ u64 splat2(float x) { return pack2(x, x); }
__device__ __forceinline__ u64 ffma2(u64 a, u64 b, u64 c) {
    u64 d; asm("fma.rn.f32x2 %0, %1, %2, %3;" : "=l"(d) : "l"(a), "l"(b), "l"(c)); return d;
}
__device__ __forceinline__ u64 add2(u64 a, u64 b) {
    u64 d; asm("add.rn.f32x2 %0, %1, %2;" : "=l"(d) : "l"(a), "l"(b)); return d;
}

// ---------------- device-global precomputed state (no cudaMalloc allowed) ----
__device__ int    g_rowptr[CAP + 1];
__device__ int    g_col[E_SP];
__device__ float  g_invdeg[CAP];
__device__ float  g_G1[INV][INV];   // Wl @ F1
__device__ float  g_G2[INV][INV];   // Wr @ F1
__device__ float  g_B1[INV][INV];   // A^T @ F2
__device__ float  g_F2[INV][INV];   // F2
__device__ float  g_V[5][INV][INV]; // combined conv taps folded with F3
__device__ float  g_csF2[INV];      // column sums of F2 (for fgcn_bl term)
__device__ float  g_const[INV];     // bl@F1 + fc_b
__device__ float2 g_W2[SEQ * SEQ];  // packed (fWl[t][s], fWr[t][s])

// ---------------- fused prep: block 0 = CSR + folded matrices (all smem),
// ---------------- blocks 1..81 = W2 packing (81*256 == SEQ*SEQ) -------------
__global__ void prep_all(const int* __restrict__ gei, const int* __restrict__ fei,
                         const float* __restrict__ Wl, const float* __restrict__ bl,
                         const float* __restrict__ Wr,
                         const float* __restrict__ c1w, const float* __restrict__ c2w,
                         const float* __restrict__ fcw, const float* __restrict__ fcb,
                         const float* __restrict__ fWl, const float* __restrict__ fWr) {
    const int tid = threadIdx.x;   // 256 threads
    const int bx  = blockIdx.x;

    if (bx > 0) {
        int i = (bx - 1) * 256 + tid;
        g_W2[i] = make_float2(fWl[i], fWr[i]);
        return;
    }

    __shared__ int   s_src[E_SP];
    __shared__ int   s_dst[E_SP];
    __shared__ int   s_deg[CAP];
    __shared__ int   sc_a[256], sc_b[256];
    __shared__ int   s_fe[2 * E_FT];
    __shared__ int   s_cnt[INV][INV];
    __shared__ float s_A[INV][INV];
    __shared__ float s_fcw[48 * INV];
    __shared__ float s_Wl[INV * INV], s_Wr[INV * INV], s_bl[INV], s_fcb[INV];
    __shared__ float s_c1[INV * INV * 3], s_c2[INV * INV * 5];

    for (int e = tid; e < E_SP; e += 256) { s_src[e] = gei[e]; s_dst[e] = gei[E_SP + e]; }
    for (int i = tid; i < 2 * E_FT; i += 256) s_fe[i] = fei[i];
    for (int i = tid; i < 48 * INV; i += 256) s_fcw[i] = fcw[i];
    for (int i = tid; i < INV * INV; i += 256) { s_Wl[i] = Wl[i]; s_Wr[i] = Wr[i]; }
    for (int i = tid; i < INV * INV * 3; i += 256) s_c1[i] = c1w[i];
    for (int i = tid; i < INV * INV * 5; i += 256) s_c2[i] = c2w[i];
    if (tid < INV) { s_bl[tid] = bl[tid]; s_fcb[tid] = fcb[tid]; }
    if (tid < CAP) s_deg[tid] = 0;
    __syncthreads();

    for (int e = tid; e < E_SP; e += 256) atomicAdd(&s_deg[s_dst[e]], 1);
    __syncthreads();

    int v = (tid < CAP) ? s_deg[tid] : 0;
    sc_a[tid] = v;
    __syncthreads();
    int* cur = sc_a; int* nxt = sc_b;
    #pragma unroll
    for (int off = 1; off < 256; off <<= 1) {
        int x = cur[tid];
        if (tid >= off) x += cur[tid - off];
        nxt[tid] = x;
        __syncthreads();
        int* t = cur; cur = nxt; nxt = t;
    }
    int incl = cur[tid];
    int excl = incl - v;
    if (tid < CAP) {
        g_rowptr[tid] = excl;
        g_invdeg[tid] = 1.0f / fmaxf((float)v, 1.0f);
        if (tid == CAP - 1) g_rowptr[CAP] = incl;
    }

    if (tid < CAP) {
        int k = excl;
        #pragma unroll 8
        for (int e = 0; e < E_SP; e++)
            if (s_dst[e] == tid) g_col[k++] = s_src[e];
    }

    {
        int i = tid >> 4, j = tid & 15;
        int cnt = 0;
        #pragma unroll
        for (int e = 0; e < E_FT; e++)
            if (s_fe[E_FT + e] == i && s_fe[e] == j) cnt++;
        s_cnt[i][j] = cnt;
    }
    __syncthreads();
    {
        int i = tid >> 4, j = tid & 15;
        int dsum = 0;
        #pragma unroll
        for (int jj = 0; jj < INV; jj++) dsum += s_cnt[i][jj];
        s_A[i][j] = (float)s_cnt[i][j] / fmaxf((float)dsum, 1.0f);
    }
    __syncthreads();

    {
        int r = tid >> 4, o = tid & 15;
        float g1 = 0.f, g2 = 0.f, b1 = 0.f;
        #pragma unroll
        for (int i = 0; i < INV; i++) {
            float f1 = s_fcw[i * INV + o];
            float f2 = s_fcw[(INV + i) * INV + o];
            g1 += s_Wl[r * INV + i] * f1;
            g2 += s_Wr[r * INV + i] * f1;
            b1 += s_A[i][r] * f2;
        }
        g_G1[r][o] = g1; g_G2[r][o] = g2; g_B1[r][o] = b1;
        g_F2[r][o] = s_fcw[(INV + r) * INV + o];
        #pragma unroll
        for (int k = 0; k < 5; k++) {
            float vv = 0.f;
            #pragma unroll
            for (int o2 = 0; o2 < INV; o2++) {
                float w5 = s_c2[(o2 * INV + r) * 5 + k];
                if (k >= 1 && k <= 3) w5 += s_c1[(o2 * INV + r) * 3 + (k - 1)];
                vv += w5 * s_fcw[(32 + o2) * INV + o];
            }
            g_V[k][r][o] = vv;
        }
        if (r == 0) {
            float cs = 0.f, cv = 0.f;
            #pragma unroll
            for (int i = 0; i < INV; i++) {
                cs += s_fcw[(INV + i) * INV + o];
                cv += s_bl[i] * s_fcw[i * INV + o];
            }
            g_csF2[o] = cs;
            g_const[o] = cv + s_fcb[o];
        }
    }
}

// ---------------- main fused kernel: one (b,c) slice per block --------------
// 160 threads; tid<144 active: sp = tid>>2 (in [0,36)), h = tid&3.
// Each thread owns s ∈ {sp, sp+36, sp+72, sp+108} x channels [4h, 4h+4).
// Spatial gather is deduplicated: thread tid computes the 16-ch mean for
// s=tid once, staged through the sYA buffer before YA overwrites it.
__global__ __launch_bounds__(NTHR, 5)
void stconv_kernel(const float* __restrict__ src,
                   const float* __restrict__ fbl,
                   float* __restrict__ out) {
    __shared__ __align__(16) float sX[INV][XSTR];
    __shared__ __align__(16) float sYA[SEQ][YSTR];   // first holds mean, then YA
    __shared__ __align__(16) float sYF[SEQ][YSTR];
    __shared__ __align__(16) float sG1[INV][INV], sG2[INV][INV], sB1[INV][INV], sF2[INV][INV];
    __shared__ __align__(16) float sV[5][INV][INV];
    __shared__ __align__(16) float sCs[INV], sC0[INV];

    const int c = blockIdx.x, b = blockIdx.y;
    const int tid = threadIdx.x;
    const bool act = tid < 144;
    const int sp = tid >> 2;    // 0..35
    const int h  = tid & 3;     // channel quarter
    const int base = ((b * CAP + c) * SEQ) * INV;

    for (int idx = tid; idx < INV * INV; idx += NTHR) {
        int r = idx >> 4, o = idx & 15;
        sG1[r][o] = g_G1[r][o]; sG2[r][o] = g_G2[r][o];
        sB1[r][o] = g_B1[r][o]; sF2[r][o] = g_F2[r][o];
        #pragma unroll
        for (int k = 0; k < 5; k++) sV[k][r][o] = g_V[k][r][o];
        if (r == 0) { sCs[o] = g_csF2[o]; sC0[o] = g_const[o]; }
    }
    if (tid < 2 * INV) {
        sX[tid >> 1][tid & 1] = 0.f;
    } else if (tid < 2 * INV + (XSTR - SEQ - SOFF) * INV) {
        int g = tid - 2 * INV;
        sX[g % INV][SEQ + SOFF + g / INV] = 0.f;
    }

    if (act) {  // X load: thread tid loads row s=tid, transposed into sX
        const float4* p = (const float4*)(src + base + tid * INV);
        float4 a0 = p[0], a1 = p[1], a2 = p[2], a3 = p[3];
        int ss = tid + SOFF;
        sX[0][ss]=a0.x;  sX[1][ss]=a0.y;  sX[2][ss]=a0.z;  sX[3][ss]=a0.w;
        sX[4][ss]=a1.x;  sX[5][ss]=a1.y;  sX[6][ss]=a1.z;  sX[7][ss]=a1.w;
        sX[8][ss]=a2.x;  sX[9][ss]=a2.y;  sX[10][ss]=a2.z; sX[11][ss]=a2.w;
        sX[12][ss]=a3.x; sX[13][ss]=a3.y; sX[14][ss]=a3.z; sX[15][ss]=a3.w;
    }
    __syncthreads();

    const int r0 = g_rowptr[c], r1 = g_rowptr[c + 1];
    const float sc = g_invdeg[c];

    // ---- phase 2: deduplicated spatial gather; mean for s=tid -> sYA[s] ----
    if (act) {
        const int s = tid;
        float4 m0 = {0,0,0,0}, m1 = {0,0,0,0}, m2 = {0,0,0,0}, m3 = {0,0,0,0};
        for (int e = r0; e < r1; e++) {
            int nb = g_col[e];
            const float4* p = (const float4*)(src + ((b * CAP + nb) * SEQ + s) * INV);
            float4 a0 = __ldg(p), a1 = __ldg(p + 1), a2 = __ldg(p + 2), a3 = __ldg(p + 3);
            m0.x+=a0.x; m0.y+=a0.y; m0.z+=a0.z; m0.w+=a0.w;
            m1.x+=a1.x; m1.y+=a1.y; m1.z+=a1.z; m1.w+=a1.w;
            m2.x+=a2.x; m2.y+=a2.y; m2.z+=a2.z; m2.w+=a2.w;
            m3.x+=a3.x; m3.y+=a3.y; m3.z+=a3.z; m3.w+=a3.w;
        }
        float4* mw = (float4*)sYA[s];
        mw[0] = make_float4(m0.x*sc, m0.y*sc, m0.z*sc, m0.w*sc);
        mw[1] = make_float4(m1.x*sc, m1.y*sc, m1.z*sc, m1.w*sc);
        mw[2] = make_float4(m2.x*sc, m2.y*sc, m2.z*sc, m2.w*sc);
        mw[3] = make_float4(m3.x*sc, m3.y*sc, m3.z*sc, m3.w*sc);
    }
    __syncthreads();

    u64 acc[4][2];   // [m][2 x f32x2 = 4 channels]
    if (act) {
        // ---- phase 3: constant init + spatial fold (reads mean from sYA) ----
        #pragma unroll
        for (int m = 0; m < 4; m++) {
            const int s = sp + 36 * m;
            u64 fbls = splat2(__ldg(fbl + s));
            ulonglong2 c0 = ((const ulonglong2*)sC0)[h];
            ulonglong2 cs4 = ((const ulonglong2*)sCs)[h];
            acc[m][0] = ffma2(fbls, cs4.x, c0.x);
            acc[m][1] = ffma2(fbls, cs4.y, c0.y);
        }
        #pragma unroll
        for (int j = 0; j < 16; j++) {
            ulonglong2 g1 = ((const ulonglong2*)sG1[j])[h];
            ulonglong2 g2 = ((const ulonglong2*)sG2[j])[h];
            #pragma unroll
            for (int m = 0; m < 4; m++) {
                const int s = sp + 36 * m;
                u64 mm = splat2(sYA[s][j]);          // mean value
                u64 xv = splat2(sX[j][s + SOFF]);
                acc[m][0] = ffma2(mm, g1.x, acc[m][0]);
                acc[m][1] = ffma2(mm, g1.y, acc[m][1]);
                acc[m][0] = ffma2(xv, g2.x, acc[m][0]);
                acc[m][1] = ffma2(xv, g2.y, acc[m][1]);
            }
        }
    }
    __syncthreads();   // fold done before sYA is overwritten

    if (act) {
        // ---- phase 4: build YA/YF (4 s, 4 ch each) and store; temporal ----
        #pragma unroll
        for (int m = 0; m < 4; m++) {
            const int s  = sp + 36 * m;
            const int ss = s + SOFF;
            u64 ya0 = 0, ya1 = 0, yf0 = 0, yf1 = 0;
            #pragma unroll
            for (int j = 0; j < 16; j++) {
                u64 xv = splat2(sX[j][ss]);
                ulonglong2 bq = ((const ulonglong2*)sB1[j])[h];
                ulonglong2 fq = ((const ulonglong2*)sF2[j])[h];
                ya0 = ffma2(xv, bq.x, ya0); ya1 = ffma2(xv, bq.y, ya1);
                yf0 = ffma2(xv, fq.x, yf0); yf1 = ffma2(xv, fq.y, yf1);
            }
            ((ulonglong2*)sYA[s])[h] = make_ulonglong2(ya0, ya1);
            ((ulonglong2*)sYF[s])[h] = make_ulonglong2(yf0, yf1);
        }

        // temporal: V chunk shared across the 4 s-positions
        #pragma unroll
        for (int k = 0; k < 5; k++) {
            #pragma unroll
            for (int j = 0; j < 16; j++) {
                ulonglong2 vq = ((const ulonglong2*)sV[k][j])[h];
                #pragma unroll
                for (int m = 0; m < 4; m++) {
                    u64 xv = splat2(sX[j][sp + 36 * m + SOFF + k - 2]);
                    acc[m][0] = ffma2(xv, vq.x, acc[m][0]);
                    acc[m][1] = ffma2(xv, vq.y, acc[m][1]);
                }
            }
        }
    }
    __syncthreads();

    if (act) {
        // ---- big GEMM: Y chunk (32 B) shared across 4 s-positions ----
        const float2* wp = g_W2;
        #pragma unroll 4
        for (int t = 0; t < SEQ; t++) {
            ulonglong2 ya = ((const ulonglong2*)sYA[t])[h];
            ulonglong2 yf = ((const ulonglong2*)sYF[t])[h];
            #pragma unroll
            for (int m = 0; m < 4; m++) {
                float2 w = __ldg(wp + t * SEQ + sp + 36 * m);
                u64 wl = splat2(w.x), wr = splat2(w.y);
                acc[m][0] = ffma2(wl, ya.x, acc[m][0]);
                acc[m][1] = ffma2(wl, ya.y, acc[m][1]);
                acc[m][0] = ffma2(wr, yf.x, acc[m][0]);
                acc[m][1] = ffma2(wr, yf.y, acc[m][1]);
            }
        }

        // ---- out = src + contributions (x re-read from smem) ----
        const int ob = 4 * h;
        #pragma unroll
        for (int m = 0; m < 4; m++) {
            const int s  = sp + 36 * m;
            const int ss = s + SOFF;
            u64 x01 = pack2(sX[ob+0][ss], sX[ob+1][ss]);
            u64 x23 = pack2(sX[ob+2][ss], sX[ob+3][ss]);
            ulonglong2* po = (ulonglong2*)(out + base + s * INV);
            po[h] = make_ulonglong2(add2(x01, acc[m][0]), add2(x23, acc[m][1]));
        }
    }
}

// ---------------- launch ----------------------------------------------------
extern "C" void kernel_launch(void* const* d_in, const int* in_sizes, int n_in,
                              void* d_out, int out_size) {
    const float* src = (const float*)d_in[0];
    const int*   gei = (const int*)d_in[1];
    const int*   fei = (const int*)d_in[2];
    const float* Wl  = (const float*)d_in[3];
    const float* bl  = (const float*)d_in[4];
    const float* Wr  = (const float*)d_in[5];
    const float* fWl = (const float*)d_in[6];
    const float* fbl = (const float*)d_in[7];
    const float* fWr = (const float*)d_in[8];
    const float* c1w = (const float*)d_in[9];
    const float* c2w = (const float*)d_in[10];
    const float* fcw = (const float*)d_in[11];
    const float* fcb = (const float*)d_in[12];

    prep_all<<<1 + (SEQ * SEQ) / 256, 256>>>(gei, fei, Wl, bl, Wr, c1w, c2w, fcw, fcb, fWl, fWr);
    dim3 grid(CAP, BZ);
    stconv_kernel<<<grid, NTHR>>>(src, fbl, (float*)d_out);
}

// round 13
// speedup vs baseline: 1.5340x; 1.5340x over previous
#include <cuda_runtime.h>

#define BZ   32
#define CAP  134
#define SEQ  144
#define INV  16
#define E_SP 1072
#define E_FT 64
#define NTHR 160
#define XSTR 152   // 2 zero guard cols + 144 + pad (sX row stride)
#define SOFF 2     // guard offset
#define YSTR 20    // padded row stride for sYA/sYF (80B rows, 16B-aligned)

typedef unsigned long long u64;

// ---------------- f32x2 packed helpers (sm_103a) -----------------------------
__device__ __forceinline__ u64 pack2(float x, float y) {
    u64 r; asm("mov.b64 %0, {%1, %2};" : "=l"(r) : "f"(x), "f"(y)); return r;
}
__device__ __forceinline__ u64 splat2(float x) { return pack2(x, x); }
__device__ __forceinline__ u64 ffma2(u64 a, u64 b, u64 c) {
    u64 d; asm("fma.rn.f32x2 %0, %1, %2, %3;" : "=l"(d) : "l"(a), "l"(b), "l"(c)); return d;
}
__device__ __forceinline__ u64 add2(u64 a, u64 b) {
    u64 d; asm("add.rn.f32x2 %0, %1, %2;" : "=l"(d) : "l"(a), "l"(b)); return d;
}

// ---------------- device-global precomputed state (no cudaMalloc allowed) ----
__device__ int    g_rowptr[CAP + 1];
__device__ int    g_col[E_SP];
__device__ float  g_invdeg[CAP];
__device__ float  g_G1[INV][INV];   // Wl @ F1
__device__ float  g_G2[INV][INV];   // Wr @ F1
__device__ float  g_B1[INV][INV];   // A^T @ F2
__device__ float  g_F2[INV][INV];   // F2
__device__ float  g_V[5][INV][INV]; // combined conv taps folded with F3
__device__ float  g_csF2[INV];      // column sums of F2 (for fgcn_bl term)
__device__ float  g_const[INV];     // bl@F1 + fc_b
__device__ float2 g_W2[SEQ * SEQ];  // packed (fWl[t][s], fWr[t][s])

// ---------------- fused prep: block 0 = CSR + folded matrices (all smem),
// ---------------- blocks 1..81 = W2 packing (81*256 == SEQ*SEQ) -------------
__global__ void prep_all(const int* __restrict__ gei, const int* __restrict__ fei,
                         const float* __restrict__ Wl, const float* __restrict__ bl,
                         const float* __restrict__ Wr,
                         const float* __restrict__ c1w, const float* __restrict__ c2w,
                         const float* __restrict__ fcw, const float* __restrict__ fcb,
                         const float* __restrict__ fWl, const float* __restrict__ fWr) {
    const int tid = threadIdx.x;   // 256 threads
    const int bx  = blockIdx.x;

    if (bx > 0) {
        int i = (bx - 1) * 256 + tid;
        g_W2[i] = make_float2(fWl[i], fWr[i]);
        return;
    }

    __shared__ int   s_src[E_SP];
    __shared__ int   s_dst[E_SP];
    __shared__ int   s_deg[CAP];
    __shared__ int   sc_a[256], sc_b[256];
    __shared__ int   s_fe[2 * E_FT];
    __shared__ int   s_cnt[INV][INV];
    __shared__ float s_A[INV][INV];
    __shared__ float s_fcw[48 * INV];
    __shared__ float s_Wl[INV * INV], s_Wr[INV * INV], s_bl[INV], s_fcb[INV];
    __shared__ float s_c1[INV * INV * 3], s_c2[INV * INV * 5];

    for (int e = tid; e < E_SP; e += 256) { s_src[e] = gei[e]; s_dst[e] = gei[E_SP + e]; }
    for (int i = tid; i < 2 * E_FT; i += 256) s_fe[i] = fei[i];
    for (int i = tid; i < 48 * INV; i += 256) s_fcw[i] = fcw[i];
    for (int i = tid; i < INV * INV; i += 256) { s_Wl[i] = Wl[i]; s_Wr[i] = Wr[i]; }
    for (int i = tid; i < INV * INV * 3; i += 256) s_c1[i] = c1w[i];
    for (int i = tid; i < INV * INV * 5; i += 256) s_c2[i] = c2w[i];
    if (tid < INV) { s_bl[tid] = bl[tid]; s_fcb[tid] = fcb[tid]; }
    if (tid < CAP) s_deg[tid] = 0;
    __syncthreads();

    for (int e = tid; e < E_SP; e += 256) atomicAdd(&s_deg[s_dst[e]], 1);
    __syncthreads();

    int v = (tid < CAP) ? s_deg[tid] : 0;
    sc_a[tid] = v;
    __syncthreads();
    int* cur = sc_a; int* nxt = sc_b;
    #pragma unroll
    for (int off = 1; off < 256; off <<= 1) {
        int x = cur[tid];
        if (tid >= off) x += cur[tid - off];
        nxt[tid] = x;
        __syncthreads();
        int* t = cur; cur = nxt; nxt = t;
    }
    int incl = cur[tid];
    int excl = incl - v;
    if (tid < CAP) {
        g_rowptr[tid] = excl;
        g_invdeg[tid] = 1.0f / fmaxf((float)v, 1.0f);
        if (tid == CAP - 1) g_rowptr[CAP] = incl;
    }

    if (tid < CAP) {
        int k = excl;
        #pragma unroll 8
        for (int e = 0; e < E_SP; e++)
            if (s_dst[e] == tid) g_col[k++] = s_src[e];
    }

    {
        int i = tid >> 4, j = tid & 15;
        int cnt = 0;
        #pragma unroll
        for (int e = 0; e < E_FT; e++)
            if (s_fe[E_FT + e] == i && s_fe[e] == j) cnt++;
        s_cnt[i][j] = cnt;
    }
    __syncthreads();
    {
        int i = tid >> 4, j = tid & 15;
        int dsum = 0;
        #pragma unroll
        for (int jj = 0; jj < INV; jj++) dsum += s_cnt[i][jj];
        s_A[i][j] = (float)s_cnt[i][j] / fmaxf((float)dsum, 1.0f);
    }
    __syncthreads();

    {
        int r = tid >> 4, o = tid & 15;
        float g1 = 0.f, g2 = 0.f, b1 = 0.f;
        #pragma unroll
        for (int i = 0; i < INV; i++) {
            float f1 = s_fcw[i * INV + o];
            float f2 = s_fcw[(INV + i) * INV + o];
            g1 += s_Wl[r * INV + i] * f1;
            g2 += s_Wr[r * INV + i] * f1;
            b1 += s_A[i][r] * f2;
        }
        g_G1[r][o] = g1; g_G2[r][o] = g2; g_B1[r][o] = b1;
        g_F2[r][o] = s_fcw[(INV + r) * INV + o];
        #pragma unroll
        for (int k = 0; k < 5; k++) {
            float vv = 0.f;
            #pragma unroll
            for (int o2 = 0; o2 < INV; o2++) {
                float w5 = s_c2[(o2 * INV + r) * 5 + k];
                if (k >= 1 && k <= 3) w5 += s_c1[(o2 * INV + r) * 3 + (k - 1)];
                vv += w5 * s_fcw[(32 + o2) * INV + o];
            }
            g_V[k][r][o] = vv;
        }
        if (r == 0) {
            float cs = 0.f, cv = 0.f;
            #pragma unroll
            for (int i = 0; i < INV; i++) {
                cs += s_fcw[(INV + i) * INV + o];
                cv += s_bl[i] * s_fcw[i * INV + o];
            }
            g_csF2[o] = cs;
            g_const[o] = cv + s_fcb[o];
        }
    }
}

// ---------------- main fused kernel: one (b,c) slice per block --------------
// 160 threads; tid<144 active: sp = tid>>2 (in [0,36)), h = tid&3.
// Each thread owns s ∈ {sp, sp+36, sp+72, sp+108} x channels [4h, 4h+4).
// Gather is per-thread redundant (h-quad lanes broadcast-share each 64B row),
// folded immediately — the R11 cache-benign pattern; no staging, 2 syncs total.
__global__ __launch_bounds__(NTHR, 5)
void stconv_kernel(const float* __restrict__ src,
                   const float* __restrict__ fbl,
                   float* __restrict__ out) {
    __shared__ __align__(16) float sX[INV][XSTR];
    __shared__ __align__(16) float sYA[SEQ][YSTR];
    __shared__ __align__(16) float sYF[SEQ][YSTR];
    __shared__ __align__(16) float sG1[INV][INV], sG2[INV][INV], sB1[INV][INV], sF2[INV][INV];
    __shared__ __align__(16) float sV[5][INV][INV];
    __shared__ __align__(16) float sCs[INV], sC0[INV];

    const int c = blockIdx.x, b = blockIdx.y;
    const int tid = threadIdx.x;
    const bool act = tid < 144;
    const int sp = tid >> 2;    // 0..35
    const int h  = tid & 3;     // channel quarter
    const int base = ((b * CAP + c) * SEQ) * INV;

    for (int idx = tid; idx < INV * INV; idx += NTHR) {
        int r = idx >> 4, o = idx & 15;
        sG1[r][o] = g_G1[r][o]; sG2[r][o] = g_G2[r][o];
        sB1[r][o] = g_B1[r][o]; sF2[r][o] = g_F2[r][o];
        #pragma unroll
        for (int k = 0; k < 5; k++) sV[k][r][o] = g_V[k][r][o];
        if (r == 0) { sCs[o] = g_csF2[o]; sC0[o] = g_const[o]; }
    }
    if (tid < 2 * INV) {
        sX[tid >> 1][tid & 1] = 0.f;
    } else if (tid < 2 * INV + (XSTR - SEQ - SOFF) * INV) {
        int g = tid - 2 * INV;
        sX[g % INV][SEQ + SOFF + g / INV] = 0.f;
    }

    if (act) {  // X load: thread tid loads row s=tid, transposed into sX
        const float4* p = (const float4*)(src + base + tid * INV);
        float4 a0 = p[0], a1 = p[1], a2 = p[2], a3 = p[3];
        int ss = tid + SOFF;
        sX[0][ss]=a0.x;  sX[1][ss]=a0.y;  sX[2][ss]=a0.z;  sX[3][ss]=a0.w;
        sX[4][ss]=a1.x;  sX[5][ss]=a1.y;  sX[6][ss]=a1.z;  sX[7][ss]=a1.w;
        sX[8][ss]=a2.x;  sX[9][ss]=a2.y;  sX[10][ss]=a2.z; sX[11][ss]=a2.w;
        sX[12][ss]=a3.x; sX[13][ss]=a3.y; sX[14][ss]=a3.z; sX[15][ss]=a3.w;
    }
    __syncthreads();

    u64 acc[4][2];   // [m][2 x f32x2 = 4 channels]
    if (act) {
        const int r0 = g_rowptr[c], r1 = g_rowptr[c + 1];
        const float sc = g_invdeg[c];

        // ---- per s-position: const init + redundant gather + spatial fold ----
        #pragma unroll
        for (int m = 0; m < 4; m++) {
            const int s  = sp + 36 * m;
            const int ss = s + SOFF;

            // constant + fgcn_bl term
            {
                u64 fbls = splat2(__ldg(fbl + s));
                ulonglong2 c0 = ((const ulonglong2*)sC0)[h];
                ulonglong2 cs4 = ((const ulonglong2*)sCs)[h];
                acc[m][0] = ffma2(fbls, cs4.x, c0.x);
                acc[m][1] = ffma2(fbls, cs4.y, c0.y);
            }

            // gather mean over graph neighbors (full 16 ch; quad lanes share rows)
            float4 m0 = {0,0,0,0}, m1 = {0,0,0,0}, m2 = {0,0,0,0}, m3 = {0,0,0,0};
            for (int e = r0; e < r1; e++) {
                int nb = g_col[e];
                const float4* p = (const float4*)(src + ((b * CAP + nb) * SEQ + s) * INV);
                float4 a0 = __ldg(p), a1 = __ldg(p + 1), a2 = __ldg(p + 2), a3 = __ldg(p + 3);
                m0.x+=a0.x; m0.y+=a0.y; m0.z+=a0.z; m0.w+=a0.w;
                m1.x+=a1.x; m1.y+=a1.y; m1.z+=a1.z; m1.w+=a1.w;
                m2.x+=a2.x; m2.y+=a2.y; m2.z+=a2.z; m2.w+=a2.w;
                m3.x+=a3.x; m3.y+=a3.y; m3.z+=a3.z; m3.w+=a3.w;
            }
            float mg[16] = {m0.x*sc,m0.y*sc,m0.z*sc,m0.w*sc, m1.x*sc,m1.y*sc,m1.z*sc,m1.w*sc,
                            m2.x*sc,m2.y*sc,m2.z*sc,m2.w*sc, m3.x*sc,m3.y*sc,m3.z*sc,m3.w*sc};

            // spatial fold into this thread's 4 channels
            #pragma unroll
            for (int j = 0; j < 16; j++) {
                u64 mm = splat2(mg[j]);
                u64 xv = splat2(sX[j][ss]);
                ulonglong2 g1 = ((const ulonglong2*)sG1[j])[h];
                ulonglong2 g2 = ((const ulonglong2*)sG2[j])[h];
                acc[m][0] = ffma2(mm, g1.x, acc[m][0]);
                acc[m][1] = ffma2(mm, g1.y, acc[m][1]);
                acc[m][0] = ffma2(xv, g2.x, acc[m][0]);
                acc[m][1] = ffma2(xv, g2.y, acc[m][1]);
            }
        }

        // ---- build YA/YF (4 s, 4 ch each) and store to smem ----
        #pragma unroll
        for (int m = 0; m < 4; m++) {
            const int s  = sp + 36 * m;
            const int ss = s + SOFF;
            u64 ya0 = 0, ya1 = 0, yf0 = 0, yf1 = 0;
            #pragma unroll
            for (int j = 0; j < 16; j++) {
                u64 xv = splat2(sX[j][ss]);
                ulonglong2 bq = ((const ulonglong2*)sB1[j])[h];
                ulonglong2 fq = ((const ulonglong2*)sF2[j])[h];
                ya0 = ffma2(xv, bq.x, ya0); ya1 = ffma2(xv, bq.y, ya1);
                yf0 = ffma2(xv, fq.x, yf0); yf1 = ffma2(xv, fq.y, yf1);
            }
            ((ulonglong2*)sYA[s])[h] = make_ulonglong2(ya0, ya1);
            ((ulonglong2*)sYF[s])[h] = make_ulonglong2(yf0, yf1);
        }

        // ---- temporal: V chunk shared across the 4 s-positions ----
        #pragma unroll
        for (int k = 0; k < 5; k++) {
            #pragma unroll
            for (int j = 0; j < 16; j++) {
                ulonglong2 vq = ((const ulonglong2*)sV[k][j])[h];
                #pragma unroll
                for (int m = 0; m < 4; m++) {
                    u64 xv = splat2(sX[j][sp + 36 * m + SOFF + k - 2]);
                    acc[m][0] = ffma2(xv, vq.x, acc[m][0]);
                    acc[m][1] = ffma2(xv, vq.y, acc[m][1]);
                }
            }
        }
    }
    __syncthreads();

    if (act) {
        // ---- big GEMM: Y chunk (32 B) shared across 4 s-positions ----
        const float2* wp = g_W2;
        #pragma unroll 4
        for (int t = 0; t < SEQ; t++) {
            ulonglong2 ya = ((const ulonglong2*)sYA[t])[h];
            ulonglong2 yf = ((const ulonglong2*)sYF[t])[h];
            #pragma unroll
            for (int m = 0; m < 4; m++) {
                float2 w = __ldg(wp + t * SEQ + sp + 36 * m);
                u64 wl = splat2(w.x), wr = splat2(w.y);
                acc[m][0] = ffma2(wl, ya.x, acc[m][0]);
                acc[m][1] = ffma2(wl, ya.y, acc[m][1]);
                acc[m][0] = ffma2(wr, yf.x, acc[m][0]);
                acc[m][1] = ffma2(wr, yf.y, acc[m][1]);
            }
        }

        // ---- out = src + contributions (x re-read from smem) ----
        const int ob = 4 * h;
        #pragma unroll
        for (int m = 0; m < 4; m++) {
            const int s  = sp + 36 * m;
            const int ss = s + SOFF;
            u64 x01 = pack2(sX[ob+0][ss], sX[ob+1][ss]);
            u64 x23 = pack2(sX[ob+2][ss], sX[ob+3][ss]);
            ulonglong2* po = (ulonglong2*)(out + base + s * INV);
            po[h] = make_ulonglong2(add2(x01, acc[m][0]), add2(x23, acc[m][1]));
        }
    }
}

// ---------------- launch ----------------------------------------------------
extern "C" void kernel_launch(void* const* d_in, const int* in_sizes, int n_in,
                              void* d_out, int out_size) {
    const float* src = (const float*)d_in[0];
    const int*   gei = (const int*)d_in[1];
    const int*   fei = (const int*)d_in[2];
    const float* Wl  = (const float*)d_in[3];
    const float* bl  = (const float*)d_in[4];
    const float* Wr  = (const float*)d_in[5];
    const float* fWl = (const float*)d_in[6];
    const float* fbl = (const float*)d_in[7];
    const float* fWr = (const float*)d_in[8];
    const float* c1w = (const float*)d_in[9];
    const float* c2w = (const float*)d_in[10];
    const float* fcw = (const float*)d_in[11];
    const float* fcb = (const float*)d_in[12];

    prep_all<<<1 + (SEQ * SEQ) / 256, 256>>>(gei, fei, Wl, bl, Wr, c1w, c2w, fcw, fcb, fWl, fWr);
    dim3 grid(CAP, BZ);
    stconv_kernel<<<grid, NTHR>>>(src, fbl, (float*)d_out);
}

// round 14
// speedup vs baseline: 1.9935x; 1.2995x over previous
#include <cuda_runtime.h>

#define BZ   32
#define CAP  134
#define SEQ  144
#define INV  16
#define E_SP 1072
#define E_FT 64
#define NTHR 160
#define XSTR 152   // 2 zero guard cols + 144 + pad (sX row stride)
#define SOFF 2     // guard offset
#define YSTR 20    // padded row stride for sYA/sYF

typedef unsigned long long u64;

// ---------------- f32x2 packed helpers (sm_103a) -----------------------------
__device__ __forceinline__ u64 pack2(float x, float y) {
    u64 r; asm("mov.b64 %0, {%1, %2};" : "=l"(r) : "f"(x), "f"(y)); return r;
}
__device__ __forceinline__ u64 splat2(float x) { return pack2(x, x); }
__device__ __forceinline__ u64 ffma2(u64 a, u64 b, u64 c) {
    u64 d; asm("fma.rn.f32x2 %0, %1, %2, %3;" : "=l"(d) : "l"(a), "l"(b), "l"(c)); return d;
}
__device__ __forceinline__ u64 add2(u64 a, u64 b) {
    u64 d; asm("add.rn.f32x2 %0, %1, %2;" : "=l"(d) : "l"(a), "l"(b)); return d;
}

// ---------------- device-global precomputed state (no cudaMalloc allowed) ----
__device__ int    g_rowptr[CAP + 1];
__device__ int    g_col[E_SP];
__device__ float  g_invdeg[CAP];
__device__ float  g_G1[INV][INV];
__device__ float  g_G2[INV][INV];
__device__ float  g_B1[INV][INV];
__device__ float  g_F2[INV][INV];
__device__ float  g_V[5][INV][INV];
__device__ float  g_csF2[INV];
__device__ float  g_const[INV];
// W packed for the 4-way big-GEMM mapping: g_W4[(t*36+sp)*4 + m] = (fWl[t][sp+36m], fWr[t][sp+36m])
__device__ float2 g_W4[SEQ * 36 * 4];

// ---------------- fused prep ------------------------------------------------
__global__ void prep_all(const int* __restrict__ gei, const int* __restrict__ fei,
                         const float* __restrict__ Wl, const float* __restrict__ bl,
                         const float* __restrict__ Wr,
                         const float* __restrict__ c1w, const float* __restrict__ c2w,
                         const float* __restrict__ fcw, const float* __restrict__ fcb,
                         const float* __restrict__ fWl, const float* __restrict__ fWr) {
    const int tid = threadIdx.x;   // 256 threads
    const int bx  = blockIdx.x;

    if (bx > 0) {
        int idx = (bx - 1) * 256 + tid;          // covers SEQ*36 = 5184 (t, sp) pairs
        if (idx < SEQ * 36) {
            int t = idx / 36, sp = idx % 36;
            #pragma unroll
            for (int m = 0; m < 4; m++) {
                int s = sp + 36 * m;
                g_W4[idx * 4 + m] = make_float2(fWl[t * SEQ + s], fWr[t * SEQ + s]);
            }
        }
        return;
    }

    __shared__ int   s_src[E_SP];
    __shared__ int   s_dst[E_SP];
    __shared__ int   s_deg[CAP];
    __shared__ int   sc_a[256], sc_b[256];
    __shared__ int   s_fe[2 * E_FT];
    __shared__ int   s_cnt[INV][INV];
    __shared__ float s_A[INV][INV];
    __shared__ float s_fcw[48 * INV];
    __shared__ float s_Wl[INV * INV], s_Wr[INV * INV], s_bl[INV], s_fcb[INV];
    __shared__ float s_c1[INV * INV * 3], s_c2[INV * INV * 5];

    for (int e = tid; e < E_SP; e += 256) { s_src[e] = gei[e]; s_dst[e] = gei[E_SP + e]; }
    for (int i = tid; i < 2 * E_FT; i += 256) s_fe[i] = fei[i];
    for (int i = tid; i < 48 * INV; i += 256) s_fcw[i] = fcw[i];
    for (int i = tid; i < INV * INV; i += 256) { s_Wl[i] = Wl[i]; s_Wr[i] = Wr[i]; }
    for (int i = tid; i < INV * INV * 3; i += 256) s_c1[i] = c1w[i];
    for (int i = tid; i < INV * INV * 5; i += 256) s_c2[i] = c2w[i];
    if (tid < INV) { s_bl[tid] = bl[tid]; s_fcb[tid] = fcb[tid]; }
    if (tid < CAP) s_deg[tid] = 0;
    __syncthreads();

    for (int e = tid; e < E_SP; e += 256) atomicAdd(&s_deg[s_dst[e]], 1);
    __syncthreads();

    int v = (tid < CAP) ? s_deg[tid] : 0;
    sc_a[tid] = v;
    __syncthreads();
    int* cur = sc_a; int* nxt = sc_b;
    #pragma unroll
    for (int off = 1; off < 256; off <<= 1) {
        int x = cur[tid];
        if (tid >= off) x += cur[tid - off];
        nxt[tid] = x;
        __syncthreads();
        int* t = cur; cur = nxt; nxt = t;
    }
    int incl = cur[tid];
    int excl = incl - v;
    if (tid < CAP) {
        g_rowptr[tid] = excl;
        g_invdeg[tid] = 1.0f / fmaxf((float)v, 1.0f);
        if (tid == CAP - 1) g_rowptr[CAP] = incl;
    }

    if (tid < CAP) {
        int k = excl;
        #pragma unroll 8
        for (int e = 0; e < E_SP; e++)
            if (s_dst[e] == tid) g_col[k++] = s_src[e];
    }

    {
        int i = tid >> 4, j = tid & 15;
        int cnt = 0;
        #pragma unroll
        for (int e = 0; e < E_FT; e++)
            if (s_fe[E_FT + e] == i && s_fe[e] == j) cnt++;
        s_cnt[i][j] = cnt;
    }
    __syncthreads();
    {
        int i = tid >> 4, j = tid & 15;
        int dsum = 0;
        #pragma unroll
        for (int jj = 0; jj < INV; jj++) dsum += s_cnt[i][jj];
        s_A[i][j] = (float)s_cnt[i][j] / fmaxf((float)dsum, 1.0f);
    }
    __syncthreads();

    {
        int r = tid >> 4, o = tid & 15;
        float g1 = 0.f, g2 = 0.f, b1 = 0.f;
        #pragma unroll
        for (int i = 0; i < INV; i++) {
            float f1 = s_fcw[i * INV + o];
            float f2 = s_fcw[(INV + i) * INV + o];
            g1 += s_Wl[r * INV + i] * f1;
            g2 += s_Wr[r * INV + i] * f1;
            b1 += s_A[i][r] * f2;
        }
        g_G1[r][o] = g1; g_G2[r][o] = g2; g_B1[r][o] = b1;
        g_F2[r][o] = s_fcw[(INV + r) * INV + o];
        #pragma unroll
        for (int k = 0; k < 5; k++) {
            float vv = 0.f;
            #pragma unroll
            for (int o2 = 0; o2 < INV; o2++) {
                float w5 = s_c2[(o2 * INV + r) * 5 + k];
                if (k >= 1 && k <= 3) w5 += s_c1[(o2 * INV + r) * 3 + (k - 1)];
                vv += w5 * s_fcw[(32 + o2) * INV + o];
            }
            g_V[k][r][o] = vv;
        }
        if (r == 0) {
            float cs = 0.f, cv = 0.f;
            #pragma unroll
            for (int i = 0; i < INV; i++) {
                cs += s_fcw[(INV + i) * INV + o];
                cv += s_bl[i] * s_fcw[i * INV + o];
            }
            g_csF2[o] = cs;
            g_const[o] = cv + s_fcb[o];
        }
    }
}

// ---------------- main fused kernel: one (b,c) slice per block --------------
// FRONT phase uses the R11 mapping (sp2=tid>>1, h2=tid&1: 2 s x 8 ch) — the
// proven cache-benign gather. BIG-GEMM phase remaps to 4 s x 4 ch (sp4=tid>>2,
// h4=tid&3) so each Y chunk is shared across 4 s-positions; accumulators cross
// mappings via an smem stage overlaid on sX (dead after temporal).
__global__ __launch_bounds__(NTHR, 5)
void stconv_kernel(const float* __restrict__ src,
                   const float* __restrict__ fbl,
                   float* __restrict__ out) {
    __shared__ __align__(16) float sXbuf[INV * XSTR];   // sX, later reused as sAcc[144][16]
    __shared__ __align__(16) float sYA[SEQ][YSTR];
    __shared__ __align__(16) float sYF[SEQ][YSTR];
    __shared__ __align__(16) float sG1[INV][INV], sG2[INV][INV], sB1[INV][INV], sF2[INV][INV];
    __shared__ __align__(16) float sV[5][INV][INV];
    __shared__ __align__(16) float sCs[INV], sC0[INV];

    const int c = blockIdx.x, b = blockIdx.y;
    const int tid = threadIdx.x;
    const bool act = tid < 144;
    const int sp2 = tid >> 1;   // front mapping
    const int h2  = tid & 1;
    const int q2  = 2 * h2;     // ulonglong2 index of 8-ch half
    const int base = ((b * CAP + c) * SEQ) * INV;

    float* const sAcc = sXbuf;                    // overlay (used after temporal)
    #define sXr(i) (sXbuf + (i) * XSTR)

    for (int idx = tid; idx < INV * INV; idx += NTHR) {
        int r = idx >> 4, o = idx & 15;
        sG1[r][o] = g_G1[r][o]; sG2[r][o] = g_G2[r][o];
        sB1[r][o] = g_B1[r][o]; sF2[r][o] = g_F2[r][o];
        #pragma unroll
        for (int k = 0; k < 5; k++) sV[k][r][o] = g_V[k][r][o];
        if (r == 0) { sCs[o] = g_csF2[o]; sC0[o] = g_const[o]; }
    }
    if (tid < 2 * INV) {
        sXr(tid >> 1)[tid & 1] = 0.f;
    } else if (tid < 2 * INV + (XSTR - SEQ - SOFF) * INV) {
        int g = tid - 2 * INV;
        sXr(g % INV)[SEQ + SOFF + g / INV] = 0.f;
    }

    if (act) {  // X load: thread tid loads row s=tid, transposed
        const float4* p = (const float4*)(src + base + tid * INV);
        float4 a0 = p[0], a1 = p[1], a2 = p[2], a3 = p[3];
        int ss = tid + SOFF;
        sXr(0)[ss]=a0.x;  sXr(1)[ss]=a0.y;  sXr(2)[ss]=a0.z;  sXr(3)[ss]=a0.w;
        sXr(4)[ss]=a1.x;  sXr(5)[ss]=a1.y;  sXr(6)[ss]=a1.z;  sXr(7)[ss]=a1.w;
        sXr(8)[ss]=a2.x;  sXr(9)[ss]=a2.y;  sXr(10)[ss]=a2.z; sXr(11)[ss]=a2.w;
        sXr(12)[ss]=a3.x; sXr(13)[ss]=a3.y; sXr(14)[ss]=a3.z; sXr(15)[ss]=a3.w;
    }
    __syncthreads();

    u64 acc[2][4];   // front mapping: [m][4 x f32x2 = 8 channels]
    if (act) {
        const int r0 = g_rowptr[c], r1 = g_rowptr[c + 1];
        const float sc = g_invdeg[c];

        #pragma unroll
        for (int m = 0; m < 2; m++) {
            const int s  = sp2 + 72 * m;
            const int ss = s + SOFF;

            // YA/YF half-row for (s, h2), packed f32x2
            {
                u64 ya0=0,ya1=0,ya2=0,ya3=0, yf0=0,yf1=0,yf2=0,yf3=0;
                #pragma unroll
                for (int j = 0; j < 16; j++) {
                    u64 xv = splat2(sXr(j)[ss]);
                    const ulonglong2* br = (const ulonglong2*)sB1[j];
                    const ulonglong2* fr = (const ulonglong2*)sF2[j];
                    ulonglong2 b0 = br[q2], b1 = br[q2 + 1];
                    ulonglong2 f0 = fr[q2], f1 = fr[q2 + 1];
                    ya0 = ffma2(xv, b0.x, ya0); ya1 = ffma2(xv, b0.y, ya1);
                    ya2 = ffma2(xv, b1.x, ya2); ya3 = ffma2(xv, b1.y, ya3);
                    yf0 = ffma2(xv, f0.x, yf0); yf1 = ffma2(xv, f0.y, yf1);
                    yf2 = ffma2(xv, f1.x, yf2); yf3 = ffma2(xv, f1.y, yf3);
                }
                ulonglong2* yaw = (ulonglong2*)sYA[s];
                ulonglong2* yfw = (ulonglong2*)sYF[s];
                yaw[q2] = make_ulonglong2(ya0, ya1); yaw[q2 + 1] = make_ulonglong2(ya2, ya3);
                yfw[q2] = make_ulonglong2(yf0, yf1); yfw[q2 + 1] = make_ulonglong2(yf2, yf3);
            }

            // constant + fgcn_bl term
            {
                u64 fbls = splat2(__ldg(fbl + s));
                ulonglong2 c0a = ((const ulonglong2*)sC0)[q2], c0b = ((const ulonglong2*)sC0)[q2 + 1];
                ulonglong2 csa = ((const ulonglong2*)sCs)[q2], csb = ((const ulonglong2*)sCs)[q2 + 1];
                acc[m][0] = ffma2(fbls, csa.x, c0a.x);
                acc[m][1] = ffma2(fbls, csa.y, c0a.y);
                acc[m][2] = ffma2(fbls, csb.x, c0b.x);
                acc[m][3] = ffma2(fbls, csb.y, c0b.y);
            }

            // spatial: redundant gather (pair lanes share rows) + packed fold
            {
                float4 m0 = {0,0,0,0}, m1 = {0,0,0,0}, m2 = {0,0,0,0}, m3 = {0,0,0,0};
                for (int e = r0; e < r1; e++) {
                    int nb = g_col[e];
                    const float4* p = (const float4*)(src + ((b * CAP + nb) * SEQ + s) * INV);
                    float4 a0 = __ldg(p), a1 = __ldg(p + 1), a2 = __ldg(p + 2), a3 = __ldg(p + 3);
                    m0.x+=a0.x; m0.y+=a0.y; m0.z+=a0.z; m0.w+=a0.w;
                    m1.x+=a1.x; m1.y+=a1.y; m1.z+=a1.z; m1.w+=a1.w;
                    m2.x+=a2.x; m2.y+=a2.y; m2.z+=a2.z; m2.w+=a2.w;
                    m3.x+=a3.x; m3.y+=a3.y; m3.z+=a3.z; m3.w+=a3.w;
                }
                float mg[16] = {m0.x*sc,m0.y*sc,m0.z*sc,m0.w*sc, m1.x*sc,m1.y*sc,m1.z*sc,m1.w*sc,
                                m2.x*sc,m2.y*sc,m2.z*sc,m2.w*sc, m3.x*sc,m3.y*sc,m3.z*sc,m3.w*sc};
                #pragma unroll
                for (int j = 0; j < 16; j++) {
                    u64 mm = splat2(mg[j]);
                    u64 xv = splat2(sXr(j)[ss]);
                    const ulonglong2* g1r = (const ulonglong2*)sG1[j];
                    const ulonglong2* g2r = (const ulonglong2*)sG2[j];
                    ulonglong2 g1a = g1r[q2], g1b = g1r[q2 + 1];
                    ulonglong2 g2a = g2r[q2], g2b = g2r[q2 + 1];
                    acc[m][0] = ffma2(mm, g1a.x, acc[m][0]); acc[m][1] = ffma2(mm, g1a.y, acc[m][1]);
                    acc[m][2] = ffma2(mm, g1b.x, acc[m][2]); acc[m][3] = ffma2(mm, g1b.y, acc[m][3]);
                    acc[m][0] = ffma2(xv, g2a.x, acc[m][0]); acc[m][1] = ffma2(xv, g2a.y, acc[m][1]);
                    acc[m][2] = ffma2(xv, g2b.x, acc[m][2]); acc[m][3] = ffma2(xv, g2b.y, acc[m][3]);
                }
            }
        }

        // temporal: merged over the two s-positions, packed
        {
            const int ss0 = sp2 + SOFF, ss1 = sp2 + 72 + SOFF;
            #pragma unroll
            for (int k = 0; k < 5; k++) {
                #pragma unroll
                for (int j = 0; j < 16; j++) {
                    const ulonglong2* vr = (const ulonglong2*)sV[k][j];
                    ulonglong2 va = vr[q2], vb = vr[q2 + 1];
                    u64 x0 = splat2(sXr(j)[ss0 + k - 2]);
                    u64 x1 = splat2(sXr(j)[ss1 + k - 2]);
                    acc[0][0] = ffma2(x0, va.x, acc[0][0]); acc[0][1] = ffma2(x0, va.y, acc[0][1]);
                    acc[0][2] = ffma2(x0, vb.x, acc[0][2]); acc[0][3] = ffma2(x0, vb.y, acc[0][3]);
                    acc[1][0] = ffma2(x1, va.x, acc[1][0]); acc[1][1] = ffma2(x1, va.y, acc[1][1]);
                    acc[1][2] = ffma2(x1, vb.x, acc[1][2]); acc[1][3] = ffma2(x1, vb.y, acc[1][3]);
                }
            }
        }
    }
    __syncthreads();   // all sX reads done; sYA/sYF complete

    // ---- stage accumulators into sAcc (overlays the now-dead sX) ----
    if (act) {
        #pragma unroll
        for (int m = 0; m < 2; m++) {
            const int s = sp2 + 72 * m;
            ulonglong2* pa = (ulonglong2*)(sAcc + s * 16 + 8 * h2);
            pa[0] = make_ulonglong2(acc[m][0], acc[m][1]);
            pa[1] = make_ulonglong2(acc[m][2], acc[m][3]);
        }
    }
    __syncthreads();

    if (act) {
        // ---- remap to 4 s x 4 ch, pick up staged accumulators ----
        const int sp4 = tid >> 2;   // 0..35
        const int h4  = tid & 3;
        u64 bacc[4][2];
        #pragma unroll
        for (int m = 0; m < 4; m++) {
            ulonglong2 v = *(const ulonglong2*)(sAcc + (sp4 + 36 * m) * 16 + 4 * h4);
            bacc[m][0] = v.x; bacc[m][1] = v.y;
        }

        // ---- big GEMM: Y chunk (32 B) + W quad (32 B) shared across 4 s ----
        #pragma unroll 4
        for (int t = 0; t < SEQ; t++) {
            ulonglong2 ya = ((const ulonglong2*)sYA[t])[h4];
            ulonglong2 yf = ((const ulonglong2*)sYF[t])[h4];
            const float4* wp = (const float4*)(g_W4 + (t * 36 + sp4) * 4);
            float4 wa = __ldg(wp);      // (wl0, wr0, wl1, wr1)
            float4 wb = __ldg(wp + 1);  // (wl2, wr2, wl3, wr3)
            u64 l0 = splat2(wa.x), r0_ = splat2(wa.y);
            u64 l1 = splat2(wa.z), r1_ = splat2(wa.w);
            u64 l2 = splat2(wb.x), r2_ = splat2(wb.y);
            u64 l3 = splat2(wb.z), r3_ = splat2(wb.w);
            bacc[0][0] = ffma2(l0, ya.x, bacc[0][0]); bacc[0][1] = ffma2(l0, ya.y, bacc[0][1]);
            bacc[0][0] = ffma2(r0_, yf.x, bacc[0][0]); bacc[0][1] = ffma2(r0_, yf.y, bacc[0][1]);
            bacc[1][0] = ffma2(l1, ya.x, bacc[1][0]); bacc[1][1] = ffma2(l1, ya.y, bacc[1][1]);
            bacc[1][0] = ffma2(r1_, yf.x, bacc[1][0]); bacc[1][1] = ffma2(r1_, yf.y, bacc[1][1]);
            bacc[2][0] = ffma2(l2, ya.x, bacc[2][0]); bacc[2][1] = ffma2(l2, ya.y, bacc[2][1]);
            bacc[2][0] = ffma2(r2_, yf.x, bacc[2][0]); bacc[2][1] = ffma2(r2_, yf.y, bacc[2][1]);
            bacc[3][0] = ffma2(l3, ya.x, bacc[3][0]); bacc[3][1] = ffma2(l3, ya.y, bacc[3][1]);
            bacc[3][0] = ffma2(r3_, yf.x, bacc[3][0]); bacc[3][1] = ffma2(r3_, yf.y, bacc[3][1]);
        }

        // ---- out = src + contributions (src re-read; L2-hot) ----
        const int ob4 = 4 * h4;
        #pragma unroll
        for (int m = 0; m < 4; m++) {
            const int s = sp4 + 36 * m;
            float4 xs = __ldg((const float4*)(src + base + s * INV + ob4));
            u64 x01 = pack2(xs.x, xs.y);
            u64 x23 = pack2(xs.z, xs.w);
            ulonglong2* po = (ulonglong2*)(out + base + s * INV);
            po[h4] = make_ulonglong2(add2(x01, bacc[m][0]), add2(x23, bacc[m][1]));
        }
    }
    #undef sXr
}

// ---------------- launch ----------------------------------------------------
extern "C" void kernel_launch(void* const* d_in, const int* in_sizes, int n_in,
                              void* d_out, int out_size) {
    const float* src = (const float*)d_in[0];
    const int*   gei = (const int*)d_in[1];
    const int*   fei = (const int*)d_in[2];
    const float* Wl  = (const float*)d_in[3];
    const float* bl  = (const float*)d_in[4];
    const float* Wr  = (const float*)d_in[5];
    const float* fWl = (const float*)d_in[6];
    const float* fbl = (const float*)d_in[7];
    const float* fWr = (const float*)d_in[8];
    const float* c1w = (const float*)d_in[9];
    const float* c2w = (const float*)d_in[10];
    const float* fcw = (const float*)d_in[11];
    const float* fcb = (const float*)d_in[12];

    // block 0: CSR + folds; blocks 1..21: W4 packing (ceil(5184/256)=21)
    prep_all<<<1 + (SEQ * 36 + 255) / 256, 256>>>(gei, fei, Wl, bl, Wr, c1w, c2w, fcw, fcb, fWl, fWr);
    dim3 grid(CAP, BZ);
    stconv_kernel<<<grid, NTHR>>>(src, fbl, (float*)d_out);
}

// round 17
// speedup vs baseline: 2.3731x; 1.1904x over previous
#include <cuda_runtime.h>

#define BZ   32
#define CAP  134
#define SEQ  144
#define INV  16
#define E_SP 1072
#define E_FT 64
#define NTHR 160
#define XSTR 152   // 2 zero guard cols + 144 + pad (sX row stride)
#define SOFF 2     // guard offset
#define YSTR 20    // padded row stride for sYA/sYF

typedef unsigned long long u64;

// ---------------- f32x2 packed helpers (sm_103a) -----------------------------
__device__ __forceinline__ u64 pack2(float x, float y) {
    u64 r; asm("mov.b64 %0, {%1, %2};" : "=l"(r) : "f"(x), "f"(y)); return r;
}
__device__ __forceinline__ u64 splat2(float x) { return pack2(x, x); }
__device__ __forceinline__ u64 ffma2(u64 a, u64 b, u64 c) {
    u64 d; asm("fma.rn.f32x2 %0, %1, %2, %3;" : "=l"(d) : "l"(a), "l"(b), "l"(c)); return d;
}
__device__ __forceinline__ u64 add2(u64 a, u64 b) {
    u64 d; asm("add.rn.f32x2 %0, %1, %2;" : "=l"(d) : "l"(a), "l"(b)); return d;
}

// ---------------- device-global precomputed state (no cudaMalloc allowed) ----
__device__ int    g_rowptr[CAP + 1];
__device__ int    g_col[E_SP];
__device__ float  g_invdeg[CAP];
__device__ float  g_G1[INV][INV];
__device__ float  g_G2[INV][INV];
__device__ float  g_B1[INV][INV];
__device__ float  g_F2[INV][INV];
__device__ float  g_V[5][INV][INV];
__device__ float  g_csF2[INV];
__device__ float  g_const[INV];
// W packed for the paired-s mapping: g_Wp[t*72+sp] = (fWl[t][sp], fWr[t][sp], fWl[t][sp+72], fWr[t][sp+72])
__device__ float4 g_Wp[SEQ * 72];

// ---------------- fused prep: block 0 = CSR + folded matrices (all smem),
// ---------------- blocks 1..41 = Wp packing (SEQ*72 = 10368 entries) --------
__global__ void prep_all(const int* __restrict__ gei, const int* __restrict__ fei,
                         const float* __restrict__ Wl, const float* __restrict__ bl,
                         const float* __restrict__ Wr,
                         const float* __restrict__ c1w, const float* __restrict__ c2w,
                         const float* __restrict__ fcw, const float* __restrict__ fcb,
                         const float* __restrict__ fWl, const float* __restrict__ fWr) {
    const int tid = threadIdx.x;   // 256 threads
    const int bx  = blockIdx.x;

    if (bx > 0) {
        int idx = (bx - 1) * 256 + tid;
        if (idx < SEQ * 72) {
            int t = idx / 72, sp = idx % 72;
            g_Wp[idx] = make_float4(fWl[t * SEQ + sp],      fWr[t * SEQ + sp],
                                    fWl[t * SEQ + sp + 72], fWr[t * SEQ + sp + 72]);
        }
        return;
    }

    __shared__ int   s_src[E_SP];
    __shared__ int   s_dst[E_SP];
    __shared__ int   s_deg[CAP];
    __shared__ int   sc_a[256], sc_b[256];
    __shared__ int   s_fe[2 * E_FT];
    __shared__ int   s_cnt[INV][INV];
    __shared__ float s_A[INV][INV];
    __shared__ float s_fcw[48 * INV];
    __shared__ float s_Wl[INV * INV], s_Wr[INV * INV], s_bl[INV], s_fcb[INV];
    __shared__ float s_c1[INV * INV * 3], s_c2[INV * INV * 5];

    for (int e = tid; e < E_SP; e += 256) { s_src[e] = gei[e]; s_dst[e] = gei[E_SP + e]; }
    for (int i = tid; i < 2 * E_FT; i += 256) s_fe[i] = fei[i];
    for (int i = tid; i < 48 * INV; i += 256) s_fcw[i] = fcw[i];
    for (int i = tid; i < INV * INV; i += 256) { s_Wl[i] = Wl[i]; s_Wr[i] = Wr[i]; }
    for (int i = tid; i < INV * INV * 3; i += 256) s_c1[i] = c1w[i];
    for (int i = tid; i < INV * INV * 5; i += 256) s_c2[i] = c2w[i];
    if (tid < INV) { s_bl[tid] = bl[tid]; s_fcb[tid] = fcb[tid]; }
    if (tid < CAP) s_deg[tid] = 0;
    __syncthreads();

    for (int e = tid; e < E_SP; e += 256) atomicAdd(&s_deg[s_dst[e]], 1);
    __syncthreads();

    int v = (tid < CAP) ? s_deg[tid] : 0;
    sc_a[tid] = v;
    __syncthreads();
    int* cur = sc_a; int* nxt = sc_b;
    #pragma unroll
    for (int off = 1; off < 256; off <<= 1) {
        int x = cur[tid];
        if (tid >= off) x += cur[tid - off];
        nxt[tid] = x;
        __syncthreads();
        int* t = cur; cur = nxt; nxt = t;
    }
    int incl = cur[tid];
    int excl = incl - v;
    if (tid < CAP) {
        g_rowptr[tid] = excl;
        g_invdeg[tid] = 1.0f / fmaxf((float)v, 1.0f);
        if (tid == CAP - 1) g_rowptr[CAP] = incl;
    }

    if (tid < CAP) {
        int k = excl;
        #pragma unroll 8
        for (int e = 0; e < E_SP; e++)
            if (s_dst[e] == tid) g_col[k++] = s_src[e];
    }

    {
        int i = tid >> 4, j = tid & 15;
        int cnt = 0;
        #pragma unroll
        for (int e = 0; e < E_FT; e++)
            if (s_fe[E_FT + e] == i && s_fe[e] == j) cnt++;
        s_cnt[i][j] = cnt;
    }
    __syncthreads();
    {
        int i = tid >> 4, j = tid & 15;
        int dsum = 0;
        #pragma unroll
        for (int jj = 0; jj < INV; jj++) dsum += s_cnt[i][jj];
        s_A[i][j] = (float)s_cnt[i][j] / fmaxf((float)dsum, 1.0f);
    }
    __syncthreads();

    {
        int r = tid >> 4, o = tid & 15;
        float g1 = 0.f, g2 = 0.f, b1 = 0.f;
        #pragma unroll
        for (int i = 0; i < INV; i++) {
            float f1 = s_fcw[i * INV + o];
            float f2 = s_fcw[(INV + i) * INV + o];
            g1 += s_Wl[r * INV + i] * f1;
            g2 += s_Wr[r * INV + i] * f1;
            b1 += s_A[i][r] * f2;
        }
        g_G1[r][o] = g1; g_G2[r][o] = g2; g_B1[r][o] = b1;
        g_F2[r][o] = s_fcw[(INV + r) * INV + o];
        #pragma unroll
        for (int k = 0; k < 5; k++) {
            float vv = 0.f;
            #pragma unroll
            for (int o2 = 0; o2 < INV; o2++) {
                float w5 = s_c2[(o2 * INV + r) * 5 + k];
                if (k >= 1 && k <= 3) w5 += s_c1[(o2 * INV + r) * 3 + (k - 1)];
                vv += w5 * s_fcw[(32 + o2) * INV + o];
            }
            g_V[k][r][o] = vv;
        }
        if (r == 0) {
            float cs = 0.f, cv = 0.f;
            #pragma unroll
            for (int i = 0; i < INV; i++) {
                cs += s_fcw[(INV + i) * INV + o];
                cv += s_bl[i] * s_fcw[i * INV + o];
            }
            g_csF2[o] = cs;
            g_const[o] = cv + s_fcb[o];
        }
    }
}

// ---------------- main fused kernel: one (b,c) slice per block --------------
// R11 mapping throughout: tid<144 active, sp = tid>>1, h = tid&1;
// thread owns s ∈ {sp, sp+72} x channels [8h, 8h+8).
// Changes vs R11: (1) YA/YF build shares B1/F2 chunk loads across both s;
// (2) big-GEMM W is one LDG.128 per t (packed pairs). Math order identical.
__global__ __launch_bounds__(NTHR, 5)
void stconv_kernel(const float* __restrict__ src,
                   const float* __restrict__ fbl,
                   float* __restrict__ out) {
    __shared__ __align__(16) float sX[INV][XSTR];
    __shared__ __align__(16) float sYA[SEQ][YSTR];
    __shared__ __align__(16) float sYF[SEQ][YSTR];
    __shared__ __align__(16) float sG1[INV][INV], sG2[INV][INV], sB1[INV][INV], sF2[INV][INV];
    __shared__ __align__(16) float sV[5][INV][INV];
    __shared__ __align__(16) float sCs[INV], sC0[INV];

    const int c = blockIdx.x, b = blockIdx.y;
    const int tid = threadIdx.x;
    const bool act = tid < 144;
    const int sp = tid >> 1;    // 0..71
    const int h  = tid & 1;
    const int q  = 2 * h;       // ulonglong2 index of this thread's 8-ch half
    const int base = ((b * CAP + c) * SEQ) * INV;

    for (int idx = tid; idx < INV * INV; idx += NTHR) {
        int r = idx >> 4, o = idx & 15;
        sG1[r][o] = g_G1[r][o]; sG2[r][o] = g_G2[r][o];
        sB1[r][o] = g_B1[r][o]; sF2[r][o] = g_F2[r][o];
        #pragma unroll
        for (int k = 0; k < 5; k++) sV[k][r][o] = g_V[k][r][o];
        if (r == 0) { sCs[o] = g_csF2[o]; sC0[o] = g_const[o]; }
    }
    if (tid < 2 * INV) {
        sX[tid >> 1][tid & 1] = 0.f;
    } else if (tid < 2 * INV + (XSTR - SEQ - SOFF) * INV) {
        int g = tid - 2 * INV;
        sX[g % INV][SEQ + SOFF + g / INV] = 0.f;
    }

    if (act) {  // X load: thread tid loads row s=tid, transposed into sX
        const float4* p = (const float4*)(src + base + tid * INV);
        float4 a0 = p[0], a1 = p[1], a2 = p[2], a3 = p[3];
        int ss = tid + SOFF;
        sX[0][ss]=a0.x;  sX[1][ss]=a0.y;  sX[2][ss]=a0.z;  sX[3][ss]=a0.w;
        sX[4][ss]=a1.x;  sX[5][ss]=a1.y;  sX[6][ss]=a1.z;  sX[7][ss]=a1.w;
        sX[8][ss]=a2.x;  sX[9][ss]=a2.y;  sX[10][ss]=a2.z; sX[11][ss]=a2.w;
        sX[12][ss]=a3.x; sX[13][ss]=a3.y; sX[14][ss]=a3.z; sX[15][ss]=a3.w;
    }
    __syncthreads();

    u64 acc[2][4];   // [m][4 x f32x2 = 8 channels]
    if (act) {
        const int ss0 = sp + SOFF, ss1 = sp + 72 + SOFF;

        // ---- YA for both s-positions (B1 chunk loaded once per j) ----
        {
            u64 a00=0,a01=0,a02=0,a03=0, a10=0,a11=0,a12=0,a13=0;
            #pragma unroll
            for (int j = 0; j < 16; j++) {
                u64 x0 = splat2(sX[j][ss0]);
                u64 x1 = splat2(sX[j][ss1]);
                const ulonglong2* br = (const ulonglong2*)sB1[j];
                ulonglong2 b0 = br[q], b1 = br[q + 1];
                a00 = ffma2(x0, b0.x, a00); a01 = ffma2(x0, b0.y, a01);
                a02 = ffma2(x0, b1.x, a02); a03 = ffma2(x0, b1.y, a03);
                a10 = ffma2(x1, b0.x, a10); a11 = ffma2(x1, b0.y, a11);
                a12 = ffma2(x1, b1.x, a12); a13 = ffma2(x1, b1.y, a13);
            }
            ulonglong2* y0 = (ulonglong2*)sYA[sp];
            ulonglong2* y1 = (ulonglong2*)sYA[sp + 72];
            y0[q] = make_ulonglong2(a00, a01); y0[q + 1] = make_ulonglong2(a02, a03);
            y1[q] = make_ulonglong2(a10, a11); y1[q + 1] = make_ulonglong2(a12, a13);
        }
        // ---- YF for both s-positions (F2 chunk loaded once per j) ----
        {
            u64 a00=0,a01=0,a02=0,a03=0, a10=0,a11=0,a12=0,a13=0;
            #pragma unroll
            for (int j = 0; j < 16; j++) {
                u64 x0 = splat2(sX[j][ss0]);
                u64 x1 = splat2(sX[j][ss1]);
                const ulonglong2* fr = (const ulonglong2*)sF2[j];
                ulonglong2 f0 = fr[q], f1 = fr[q + 1];
                a00 = ffma2(x0, f0.x, a00); a01 = ffma2(x0, f0.y, a01);
                a02 = ffma2(x0, f1.x, a02); a03 = ffma2(x0, f1.y, a03);
                a10 = ffma2(x1, f0.x, a10); a11 = ffma2(x1, f0.y, a11);
                a12 = ffma2(x1, f1.x, a12); a13 = ffma2(x1, f1.y, a13);
            }
            ulonglong2* y0 = (ulonglong2*)sYF[sp];
            ulonglong2* y1 = (ulonglong2*)sYF[sp + 72];
            y0[q] = make_ulonglong2(a00, a01); y0[q + 1] = make_ulonglong2(a02, a03);
            y1[q] = make_ulonglong2(a10, a11); y1[q + 1] = make_ulonglong2(a12, a13);
        }

        const int r0 = g_rowptr[c], r1 = g_rowptr[c + 1];
        const float sc = g_invdeg[c];

        // ---- per s-position: const init + redundant gather + spatial fold ----
        #pragma unroll
        for (int m = 0; m < 2; m++) {
            const int s  = sp + 72 * m;
            const int ss = s + SOFF;

            {
                u64 fbls = splat2(__ldg(fbl + s));
                ulonglong2 c0a = ((const ulonglong2*)sC0)[q], c0b = ((const ulonglong2*)sC0)[q + 1];
                ulonglong2 csa = ((const ulonglong2*)sCs)[q], csb = ((const ulonglong2*)sCs)[q + 1];
                acc[m][0] = ffma2(fbls, csa.x, c0a.x);
                acc[m][1] = ffma2(fbls, csa.y, c0a.y);
                acc[m][2] = ffma2(fbls, csb.x, c0b.x);
                acc[m][3] = ffma2(fbls, csb.y, c0b.y);
            }

            float4 m0 = {0,0,0,0}, m1 = {0,0,0,0}, m2 = {0,0,0,0}, m3 = {0,0,0,0};
            for (int e = r0; e < r1; e++) {
                int nb = g_col[e];
                const float4* p = (const float4*)(src + ((b * CAP + nb) * SEQ + s) * INV);
                float4 a0 = __ldg(p), a1 = __ldg(p + 1), a2 = __ldg(p + 2), a3 = __ldg(p + 3);
                m0.x+=a0.x; m0.y+=a0.y; m0.z+=a0.z; m0.w+=a0.w;
                m1.x+=a1.x; m1.y+=a1.y; m1.z+=a1.z; m1.w+=a1.w;
                m2.x+=a2.x; m2.y+=a2.y; m2.z+=a2.z; m2.w+=a2.w;
                m3.x+=a3.x; m3.y+=a3.y; m3.z+=a3.z; m3.w+=a3.w;
            }
            float mg[16] = {m0.x*sc,m0.y*sc,m0.z*sc,m0.w*sc, m1.x*sc,m1.y*sc,m1.z*sc,m1.w*sc,
                            m2.x*sc,m2.y*sc,m2.z*sc,m2.w*sc, m3.x*sc,m3.y*sc,m3.z*sc,m3.w*sc};
            #pragma unroll
            for (int j = 0; j < 16; j++) {
                u64 mm = splat2(mg[j]);
                u64 xv = splat2(sX[j][ss]);
                const ulonglong2* g1r = (const ulonglong2*)sG1[j];
                const ulonglong2* g2r = (const ulonglong2*)sG2[j];
                ulonglong2 g1a = g1r[q], g1b = g1r[q + 1];
                ulonglong2 g2a = g2r[q], g2b = g2r[q + 1];
                acc[m][0] = ffma2(mm, g1a.x, acc[m][0]); acc[m][1] = ffma2(mm, g1a.y, acc[m][1]);
                acc[m][2] = ffma2(mm, g1b.x, acc[m][2]); acc[m][3] = ffma2(mm, g1b.y, acc[m][3]);
                acc[m][0] = ffma2(xv, g2a.x, acc[m][0]); acc[m][1] = ffma2(xv, g2a.y, acc[m][1]);
                acc[m][2] = ffma2(xv, g2b.x, acc[m][2]); acc[m][3] = ffma2(xv, g2b.y, acc[m][3]);
            }
        }

        // ---- temporal: V chunk shared across the two s-positions ----
        #pragma unroll
        for (int k = 0; k < 5; k++) {
            #pragma unroll
            for (int j = 0; j < 16; j++) {
                const ulonglong2* vr = (const ulonglong2*)sV[k][j];
                ulonglong2 va = vr[q], vb = vr[q + 1];
                u64 x0 = splat2(sX[j][ss0 + k - 2]);
                u64 x1 = splat2(sX[j][ss1 + k - 2]);
                acc[0][0] = ffma2(x0, va.x, acc[0][0]); acc[0][1] = ffma2(x0, va.y, acc[0][1]);
                acc[0][2] = ffma2(x0, vb.x, acc[0][2]); acc[0][3] = ffma2(x0, vb.y, acc[0][3]);
                acc[1][0] = ffma2(x1, va.x, acc[1][0]); acc[1][1] = ffma2(x1, va.y, acc[1][1]);
                acc[1][2] = ffma2(x1, vb.x, acc[1][2]); acc[1][3] = ffma2(x1, vb.y, acc[1][3]);
            }
        }
    }
    __syncthreads();

    if (act) {
        // ---- big GEMM: one LDG.128 of packed W + shared Y rows per t ----
        const float4* wp = g_Wp + sp;
        #pragma unroll 4
        for (int t = 0; t < SEQ; t++) {
            float4 w = __ldg(wp + t * 72);   // (wl_s0, wr_s0, wl_s1, wr_s1)
            u64 aX = splat2(w.x), aY = splat2(w.y);
            u64 bX = splat2(w.z), bY = splat2(w.w);
            const ulonglong2* yap = (const ulonglong2*)sYA[t];
            const ulonglong2* yfp = (const ulonglong2*)sYF[t];
            ulonglong2 u0 = yap[q], u1 = yap[q + 1];
            ulonglong2 v0 = yfp[q], v1 = yfp[q + 1];
            acc[0][0] = ffma2(aX, u0.x, acc[0][0]); acc[0][0] = ffma2(aY, v0.x, acc[0][0]);
            acc[0][1] = ffma2(aX, u0.y, acc[0][1]); acc[0][1] = ffma2(aY, v0.y, acc[0][1]);
            acc[0][2] = ffma2(aX, u1.x, acc[0][2]); acc[0][2] = ffma2(aY, v1.x, acc[0][2]);
            acc[0][3] = ffma2(aX, u1.y, acc[0][3]); acc[0][3] = ffma2(aY, v1.y, acc[0][3]);
            acc[1][0] = ffma2(bX, u0.x, acc[1][0]); acc[1][0] = ffma2(bY, v0.x, acc[1][0]);
            acc[1][1] = ffma2(bX, u0.y, acc[1][1]); acc[1][1] = ffma2(bY, v0.y, acc[1][1]);
            acc[1][2] = ffma2(bX, u1.x, acc[1][2]); acc[1][2] = ffma2(bY, v1.x, acc[1][2]);
            acc[1][3] = ffma2(bX, u1.y, acc[1][3]); acc[1][3] = ffma2(bY, v1.y, acc[1][3]);
        }

        // ---- out = src + contributions (x re-read from smem) ----
        #pragma unroll
        for (int m = 0; m < 2; m++) {
            const int s  = sp + 72 * m;
            const int ss = s + SOFF;
            const int ob = 8 * h;
            u64 x01 = pack2(sX[ob+0][ss], sX[ob+1][ss]);
            u64 x23 = pack2(sX[ob+2][ss], sX[ob+3][ss]);
            u64 x45 = pack2(sX[ob+4][ss], sX[ob+5][ss]);
            u64 x67 = pack2(sX[ob+6][ss], sX[ob+7][ss]);
            ulonglong2* po = (ulonglong2*)(out + base + s * INV);
            po[q]     = make_ulonglong2(add2(x01, acc[m][0]), add2(x23, acc[m][1]));
            po[q + 1] = make_ulonglong2(add2(x45, acc[m][2]), add2(x67, acc[m][3]));
        }
    }
}

// ---------------- launch ----------------------------------------------------
extern "C" void kernel_launch(void* const* d_in, const int* in_sizes, int n_in,
                              void* d_out, int out_size) {
    const float* src = (const float*)d_in[0];
    const int*   gei = (const int*)d_in[1];
    const int*   fei = (const int*)d_in[2];
    const float* Wl  = (const float*)d_in[3];
    const float* bl  = (const float*)d_in[4];
    const float* Wr  = (const float*)d_in[5];
    const float* fWl = (const float*)d_in[6];
    const float* fbl = (const float*)d_in[7];
    const float* fWr = (const float*)d_in[8];
    const float* c1w = (const float*)d_in[9];
    const float* c2w = (const float*)d_in[10];
    const float* fcw = (const float*)d_in[11];
    const float* fcb = (const float*)d_in[12];

    prep_all<<<1 + (SEQ * 72 + 255) / 256, 256>>>(gei, fei, Wl, bl, Wr, c1w, c2w, fcw, fcb, fWl, fWr);
    dim3 grid(CAP, BZ);
    stconv_kernel<<<grid, NTHR>>>(src, fbl, (float*)d_out);
}